// round 14
// baseline (speedup 1.0000x reference)
#include <cuda_runtime.h>
#include <cuda_bf16.h>
#include <math.h>

#define TAU_INV 10000.0f

// Output layout (float32, flattened tuple)
#define OFF_TZ1  0
#define OFF_TZ2  1024
#define OFF_FWD  2048
#define OFF_EQ   18432
#define OFF_ATTN 18433
#define OFF_ORTH 35841
#define OFF_PAR  35842
#define OFF_COM  35843
#define OFF_SPA  35844
#define OFF_SEC  35845
#define OFF_SUB  35846

typedef unsigned long long u64;

// Packed f32x2 helpers
__device__ __forceinline__ u64 f2mul(u64 a, u64 b) {
    u64 d; asm("mul.rn.f32x2 %0,%1,%2;" : "=l"(d) : "l"(a), "l"(b)); return d;
}
__device__ __forceinline__ u64 f2add(u64 a, u64 b) {
    u64 d; asm("add.rn.f32x2 %0,%1,%2;" : "=l"(d) : "l"(a), "l"(b)); return d;
}
__device__ __forceinline__ u64 f2pack(float lo, float hi) {
    u64 d; asm("mov.b64 %0,{%1,%2};" : "=l"(d) : "f"(lo), "f"(hi)); return d;
}
__device__ __forceinline__ void f2unpack(float& lo, float& hi, u64 v) {
    asm("mov.b64 {%0,%1},%2;" : "=f"(lo), "=f"(hi) : "l"(v));
}
__device__ __forceinline__ unsigned pack_bf16(float lo, float hi) {
    unsigned r; asm("cvt.rn.bf16x2.f32 %0, %1, %2;" : "=r"(r) : "f"(hi), "f"(lo)); return r;
}
__device__ __forceinline__ unsigned s2u(const void* p) {
    unsigned a; asm("{ .reg .u64 t; cvta.to.shared.u64 t, %1; cvt.u32.u64 %0, t; }" : "=r"(a) : "l"(p)); return a;
}

// Scratch — deterministic partial-sum slots, fully overwritten each replay.
__device__ float  g_diff[256 * 128 * 16];
__device__ float  g_n2[256 * 128];
__device__ double g_part_par[2176];
__device__ double g_part_orth[120];
__device__ double g_part_com[120];
__device__ double g_part_eq[128];
__device__ double g_part_sparse[256];
__device__ double g_part_sec[64];
__device__ int    g_done;          // static-init 0; last gram block resets it

// ---------------------------------------------------------------------------
// Warp-synchronous expm of 16x16 (scaling-and-squaring + 8-term Taylor).
// Lane l owns row r=l>>1, cols c0=(l&1)*8..+7.  ws = 960-float warp scratch.
// ---------------------------------------------------------------------------
__device__ __forceinline__ const float* expm16_warp(const float a8[8], float* ws,
                                                    int l, float r8[8])
{
    float* W0 = ws;
    float* W1 = ws + 320;
    float* W2 = ws + 640;
    int r = l >> 1, c0 = (l & 1) * 8;

    float cs[8];
#pragma unroll
    for (int j = 0; j < 8; j++) cs[j] = fabsf(a8[j]);
#pragma unroll
    for (int m = 2; m <= 16; m <<= 1)
#pragma unroll
        for (int j = 0; j < 8; j++) cs[j] += __shfl_xor_sync(0xffffffffu, cs[j], m);
    float nrm = fmaxf(fmaxf(fmaxf(cs[0], cs[1]), fmaxf(cs[2], cs[3])),
                      fmaxf(fmaxf(cs[4], cs[5]), fmaxf(cs[6], cs[7])));
    nrm = fmaxf(nrm, __shfl_xor_sync(0xffffffffu, nrm, 1));
    int s = 0;
    while (nrm > 0.25f && s < 40) { nrm *= 0.5f; s++; }
    float sc = ldexpf(1.0f, -s);

    float b8[8];
#pragma unroll
    for (int j = 0; j < 8; j++) {
        b8[j] = a8[j] * sc;
        r8[j] = ((c0 + j) == r ? 1.0f : 0.0f) + b8[j];
    }
    {
        float4* p0 = (float4*)&W0[r * 20 + c0];
        p0[0] = make_float4(b8[0], b8[1], b8[2], b8[3]);
        p0[1] = make_float4(b8[4], b8[5], b8[6], b8[7]);
        float4* p1 = (float4*)&W1[r * 20 + c0];
        p1[0] = make_float4(b8[0], b8[1], b8[2], b8[3]);
        p1[1] = make_float4(b8[4], b8[5], b8[6], b8[7]);
    }
    __syncwarp();

    float* Tc = W1; float* Tn = W2;
    for (int k = 2; k <= 8; k++) {
        float acc[8] = {0.f, 0.f, 0.f, 0.f, 0.f, 0.f, 0.f, 0.f};
#pragma unroll
        for (int d = 0; d < 16; d++) {
            float a = Tc[r * 20 + d];
            const float4* bv = (const float4*)&W0[d * 20 + c0];
            float4 x = bv[0], y = bv[1];
            acc[0] += a * x.x; acc[1] += a * x.y; acc[2] += a * x.z; acc[3] += a * x.w;
            acc[4] += a * y.x; acc[5] += a * y.y; acc[6] += a * y.z; acc[7] += a * y.w;
        }
        float ik = 1.0f / (float)k;
#pragma unroll
        for (int j = 0; j < 8; j++) { acc[j] *= ik; r8[j] += acc[j]; }
        float4* pt = (float4*)&Tn[r * 20 + c0];
        pt[0] = make_float4(acc[0], acc[1], acc[2], acc[3]);
        pt[1] = make_float4(acc[4], acc[5], acc[6], acc[7]);
        __syncwarp();
        float* tmp = Tc; Tc = Tn; Tn = tmp;
    }

    float* Sa = W0; float* Sb = Tn;
    {
        float4* ps = (float4*)&Sa[r * 20 + c0];
        ps[0] = make_float4(r8[0], r8[1], r8[2], r8[3]);
        ps[1] = make_float4(r8[4], r8[5], r8[6], r8[7]);
        __syncwarp();
    }
    for (int q = 0; q < s; q++) {
        float acc[8] = {0.f, 0.f, 0.f, 0.f, 0.f, 0.f, 0.f, 0.f};
#pragma unroll
        for (int d = 0; d < 16; d++) {
            float a = Sa[r * 20 + d];
            const float4* bv = (const float4*)&Sa[d * 20 + c0];
            float4 x = bv[0], y = bv[1];
            acc[0] += a * x.x; acc[1] += a * x.y; acc[2] += a * x.z; acc[3] += a * x.w;
            acc[4] += a * y.x; acc[5] += a * y.y; acc[6] += a * y.z; acc[7] += a * y.w;
        }
#pragma unroll
        for (int j = 0; j < 8; j++) r8[j] = acc[j];
        float4* ps = (float4*)&Sb[r * 20 + c0];
        ps[0] = make_float4(acc[0], acc[1], acc[2], acc[3]);
        ps[1] = make_float4(acc[4], acc[5], acc[6], acc[7]);
        __syncwarp();
        float* tmp = Sa; Sa = Sb; Sb = tmp;
    }
    return Sa;
}

// ---------------------------------------------------------------------------
// k_pre (64-thread blocks, unbounded regs):
//   bids 0..127  : pre  — warp w handles e = bid*2 + w (expm + diff + sparse)
//   bids 128..255: main — mbid = bid-128 (b = mbid&63, dir = mbid>>6)
//   bids 256..375: commut — q = bid-256
// ---------------------------------------------------------------------------
__global__ __launch_bounds__(64) void k_pre(
    const float* __restrict__ ge, const float* __restrict__ z,
    const float* __restrict__ mean, const float* __restrict__ logvar,
    const float* __restrict__ lw, const float* __restrict__ lb,
    const float* __restrict__ gum, float* __restrict__ out)
{
    __shared__ __align__(16) float sm[4480];
    int t = threadIdx.x, l = t & 31, w = t >> 5;
    int bid = blockIdx.x;

    if (bid < 128) {
        // ---- pre: expm(ge[e]) + diff + n2 + sparse
        float* sZ = sm;                 // 128*20
        float* ws = sm + 2560 + w * 960;
        int e = bid * 2 + w;
        int r = l >> 1, c0 = (l & 1) * 8;

        for (int i4 = t; i4 < 512; i4 += 64) {
            float4 v = ((const float4*)z)[i4];
            int m = i4 >> 2, q = i4 & 3;
            *(float4*)&sZ[m * 20 + q * 4] = v;
        }

        float a8[8];
        {
            const float4* gp = (const float4*)&ge[e * 256 + r * 16 + c0];
            float4 g0 = gp[0], g1 = gp[1];
            a8[0] = g0.x; a8[1] = g0.y; a8[2] = g0.z; a8[3] = g0.w;
            a8[4] = g1.x; a8[5] = g1.y; a8[6] = g1.z; a8[7] = g1.w;
        }
        float r8[8];
        const float* Rp = expm16_warp(a8, ws, l, r8);
        __syncthreads();

        float sparse_acc = 0.f;
        for (int k = 0; k < 8; k++) {
            int b = r + 16 * k;
            float acc[8] = {0.f, 0.f, 0.f, 0.f, 0.f, 0.f, 0.f, 0.f};
#pragma unroll
            for (int d = 0; d < 16; d++) {
                float zv = sZ[b * 20 + d];
                const float4* rv = (const float4*)&Rp[d * 20 + c0];
                float4 x = rv[0], y = rv[1];
                acc[0] += zv * x.x; acc[1] += zv * x.y; acc[2] += zv * x.z; acc[3] += zv * x.w;
                acc[4] += zv * y.x; acc[5] += zv * y.y; acc[6] += zv * y.z; acc[7] += zv * y.w;
            }
            const float4* zp = (const float4*)&sZ[b * 20 + c0];
            float4 z0 = zp[0], z1 = zp[1];
            float zc[8] = {z0.x, z0.y, z0.z, z0.w, z1.x, z1.y, z1.z, z1.w};
            float v8[8];
            float sum = 0.f, mx = 0.f;
#pragma unroll
            for (int j = 0; j < 8; j++) {
                v8[j] = zc[j] - acc[j];
                float v2 = v8[j] * v8[j];
                sum += v2;
                mx = fmaxf(mx, v2);
            }
            float4* dp = (float4*)&g_diff[e * 2048 + b * 16 + c0];
            dp[0] = make_float4(v8[0], v8[1], v8[2], v8[3]);
            dp[1] = make_float4(v8[4], v8[5], v8[6], v8[7]);
            sum += __shfl_xor_sync(0xffffffffu, sum, 1);
            mx = fmaxf(mx, __shfl_xor_sync(0xffffffffu, mx, 1));
            if ((l & 1) == 0) {
                g_n2[e * 128 + b] = sum;
                float sv = sum - mx;
                sparse_acc += sv * sv;
            }
        }
#pragma unroll
        for (int o = 16; o; o >>= 1) sparse_acc += __shfl_xor_sync(0xffffffffu, sparse_acc, o);
        if (l == 0) g_part_sparse[e] = (double)sparse_acc;
    } else if (bid < 256) {
        // ---- main branch (64 threads)
        int mbid = bid - 128;
        int b = mbid & 63;
        int dir = mbid >> 6;
        float* feat    = sm;           // 64
        float* probS   = sm + 64;      // 288
        float* sw      = sm + 352;     // 16
        float* fp      = sm + 368;     // 256
        float* wv      = sm + 624;     // 256
        float* z1v     = sm + 880;     // 16
        float* z2v     = sm + 896;     // 16
        float* lossArr = sm + 912;     // 16
        float* A       = sm + 928;     // 256
        float* ws      = sm + 1184;    // 960 warp0 expm scratch

        if (t < 16) {
            feat[t]      = mean[b * 16 + t];
            feat[16 + t] = __expf(0.5f * logvar[b * 16 + t]);
            feat[32 + t] = mean[(64 + b) * 16 + t];
            feat[48 + t] = __expf(0.5f * mean[(64 + b) * 16 + t]);   // ref uses mean (sic)
            z1v[t] = z[b * 16 + t];
            z2v[t] = z[(64 + b) * 16 + t];
        }
        __syncthreads();

        for (int c = t; c < 288; c += 64) {
            float acc = lb[c];
#pragma unroll 16
            for (int kk = 0; kk < 64; kk++) acc += feat[kk] * lw[c * 64 + kk];
            probS[c] = acc;
        }
        __syncthreads();

        if (t < 16) {
            int s = t;
            float l0 = probS[2 * s], l1 = probS[2 * s + 1];
            float m2 = fmaxf(l0, l1);
            float e0 = __expf(l0 - m2), e1 = __expf(l1 - m2);
            float inv = 1.0f / (e0 + e1);
            float p0 = e0 * inv, p1 = e1 * inv;
            float pm = fmaxf(p0, p1);
            float lse = pm + __logf(__expf(p0 - pm) + __expf(p1 - pm));
            float zd = z1v[s] - z2v[s];
            int tgt = (fabsf(zd) > 0.2f) ? 1 : 0;
            lossArr[s] = -((tgt ? p1 : p0) - lse);
            float g0 = gum[(b * 16 + s) * 2], g1 = gum[(b * 16 + s) * 2 + 1];
            float x0 = l0 + g0, x1 = l1 + g1;
            float mm = fmaxf(x0, x1);
            float a0 = __expf((x0 - mm) * TAU_INV);
            float a1 = __expf((x1 - mm) * TAU_INV);
            float as = a0 + a1;
            a0 /= as; a1 /= as;
            sw[s] = (a0 >= 0.5f || a1 > 0.5f) ? a1 : 0.0f;
            int base = 32 + s * 16;
            float mx = -1e30f;
            for (int u = 0; u < 16; u++) mx = fmaxf(mx, probS[base + u]);
            float smx = 0.f;
            for (int u = 0; u < 16; u++) smx += __expf(probS[base + u] - mx);
            float isv = 1.0f / smx;
            for (int u = 0; u < 16; u++) fp[s * 16 + u] = __expf(probS[base + u] - mx) * isv;
        }
        __syncthreads();

        if (dir == 0) {
            if (t == 0) {
                float sl = 0.f;
                for (int s2 = 0; s2 < 16; s2++) sl += lossArr[s2];
                g_part_sec[b] = (double)sl;
            }
            if (t < 16) out[OFF_ATTN + b * 272 + t] = sw[t];
            for (int x = t; x < 256; x += 64)
                out[OFF_ATTN + b * 272 + 16 + x] = fp[x];
        }
        for (int x = t; x < 256; x += 64) wv[x] = sw[x >> 4] * fp[x];
        __syncthreads();

        for (int x = t; x < 256; x += 64) {
            float Ssum = 0.f;
            for (int s2 = 0; s2 < 16; s2++) {
                float acc = 0.f;
#pragma unroll
                for (int u = 0; u < 16; u++)
                    acc += wv[s2 * 16 + u] * ge[(s2 * 16 + u) * 256 + x];
                if (dir == 0) out[OFF_SUB + b * 4096 + s2 * 256 + x] = acc;
                Ssum += acc;
            }
            A[x] = Ssum;
        }
        __syncthreads();   // A published; warp1 done

        if (t < 32) {
            int r = l >> 1, c0 = (l & 1) * 8;
            float sign = (dir == 0) ? 1.0f : -1.0f;
            float a8[8];
            {
                const float4* ap = (const float4*)&A[r * 16 + c0];
                float4 a0 = ap[0], a1 = ap[1];
                a8[0] = sign * a0.x; a8[1] = sign * a0.y; a8[2] = sign * a0.z; a8[3] = sign * a0.w;
                a8[4] = sign * a1.x; a8[5] = sign * a1.y; a8[6] = sign * a1.z; a8[7] = sign * a1.w;
            }
            float r8[8];
            const float* Rp = expm16_warp(a8, ws, l, r8);
            (void)Rp;
            if (dir == 0) {
                float4* op = (float4*)&out[OFF_FWD + b * 256 + r * 16 + c0];
                op[0] = make_float4(r8[0], r8[1], r8[2], r8[3]);
                op[1] = make_float4(r8[4], r8[5], r8[6], r8[7]);
            }
            const float* zsrc = (dir == 0) ? z1v : z2v;
            const float* zoth = (dir == 0) ? z2v : z1v;
            float zr = zsrc[r];
            float p8[8];
#pragma unroll
            for (int j = 0; j < 8; j++) p8[j] = zr * r8[j];
#pragma unroll
            for (int m = 2; m <= 16; m <<= 1)
#pragma unroll
                for (int j = 0; j < 8; j++) p8[j] += __shfl_xor_sync(0xffffffffu, p8[j], m);
            if (l < 2) {
                float4* tp = (float4*)&out[(dir == 0 ? OFF_TZ1 : OFF_TZ2) + b * 16 + c0];
                tp[0] = make_float4(p8[0], p8[1], p8[2], p8[3]);
                tp[1] = make_float4(p8[4], p8[5], p8[6], p8[7]);
            }
            float eqs = 0.f;
#pragma unroll
            for (int j = 0; j < 8; j++) {
                float d1 = p8[j] - zoth[c0 + j];
                eqs += d1 * d1;
            }
            eqs += __shfl_xor_sync(0xffffffffu, eqs, 1);
            if (l == 0) g_part_eq[mbid] = (double)eqs;
        }
    } else {
        // ---- commut (64 threads): q = bid-256, cumsum weight (120 - q)
        int q = bid - 256;
        float* Ga = sm;        float* Gb = sm + 256;
        float* Ha = sm + 512;  float* Hb = sm + 768;
        float* sred = sm + 1024;  // 2
        int p = q, a = 0, len = 15;
        while (p >= len) { p -= len; len--; a++; }
        int b = a + 1 + p;

        for (int idx = t; idx < 256; idx += 64) {
            int k = idx >> 4, j = idx & 15;
            Ga[idx] = ge[a * 256 + idx];
            Gb[idx] = ge[b * 256 + idx];
            Ha[idx] = ge[k * 4096 + a * 16 + j];
            Hb[idx] = ge[k * 4096 + b * 16 + j];
        }
        __syncthreads();

        float local = 0.f;
        for (int idx = t; idx < 256; idx += 64) {
            int i = idx >> 4, j = idx & 15;
            float R1 = 0.f, R2 = 0.f;
#pragma unroll
            for (int kk = 0; kk < 16; kk++) {
                R1 += Ga[i * 16 + kk] * Hb[kk * 16 + j];
                R2 += Gb[i * 16 + kk] * Ha[kk * 16 + j];
            }
            float d = R1 - R2;
            local += d * d;
        }
#pragma unroll
        for (int o = 16; o; o >>= 1) local += __shfl_xor_sync(0xffffffffu, local, o);
        if (l == 0) sred[w] = local;
        __syncthreads();
        if (t == 0)
            g_part_com[q] = (double)(sred[0] + sred[1]) * 2.0 * (double)(120 - q);
    }
}

// ---------------------------------------------------------------------------
// Tensor-core Gram tile (128x128x16) in bf16 with fp32 accumulate.
// Shared layout (floats): Pi32 @0 (1536 u32), Pj32 @1536, in2i @3072,
// in2j @3200, sred @3328.
// ---------------------------------------------------------------------------
template <bool WITH_LOG>
__device__ __forceinline__ float gram_role(const float* __restrict__ diffI,
                                           const float* __restrict__ diffJ,
                                           const float* __restrict__ n2I,
                                           const float* __restrict__ n2J,
                                           float* sm, int t)
{
    unsigned* Pi32 = (unsigned*)sm;             // 128*12 u32 (bf16x2)
    unsigned* Pj32 = (unsigned*)(sm + 1536);    // 128*12 u32
    float* in2i = sm + 3072;                    // 128
    float* in2j = sm + 3200;                    // 128

    for (int widx = t; widx < 1024; widx += 256) {
        int m = widx >> 3, kp = widx & 7;
        float2 vi = *(const float2*)&diffI[m * 16 + kp * 2];
        float2 vj = *(const float2*)&diffJ[m * 16 + kp * 2];
        Pi32[m * 12 + kp] = pack_bf16(vi.x, vi.y);
        Pj32[m * 12 + kp] = pack_bf16(vj.x, vj.y);
    }
    if (t < 128) {
        in2i[t] = 1.0f / n2I[t];
        in2j[t] = 1.0f / n2J[t];
    }
    __syncthreads();

    int lane = t & 31, w = t >> 5;
    int m0 = w * 16;

    unsigned a0, a1, a2, a3;
    {
        unsigned addr = s2u(Pi32) + (unsigned)((m0 + (lane & 15)) * 48 + (lane >> 4) * 16);
        asm volatile("ldmatrix.sync.aligned.m8n8.x4.shared.b16 {%0,%1,%2,%3}, [%4];"
                     : "=r"(a0), "=r"(a1), "=r"(a2), "=r"(a3) : "r"(addr));
    }

    int r0 = m0 + (lane >> 2);
    float ni0 = in2i[r0], ni1 = in2i[r0 + 8];
    u64 nip0 = f2pack(ni0, ni0), nip1 = f2pack(ni1, ni1);
    int cb = (lane & 3) * 2;
    unsigned pj_base = s2u(Pj32);

    const u64 eps2 = f2pack(1e-9f, 1e-9f);
    float local = 0.f;
    u64 accv = 0ull;
    float mprod = 1.0f;
    int   esum = 0;

#pragma unroll
    for (int nb = 0; nb < 16; nb++) {
        unsigned b0, b1;
        {
            int ln = lane & 15;
            unsigned addr = pj_base + (unsigned)((nb * 8 + (ln & 7)) * 48 + ((ln >> 3) & 1) * 16);
            asm volatile("ldmatrix.sync.aligned.m8n8.x2.shared.b16 {%0,%1}, [%2];"
                         : "=r"(b0), "=r"(b1) : "r"(addr));
        }
        float d0, d1, d2, d3;
        asm("mma.sync.aligned.m16n8k16.row.col.f32.bf16.bf16.f32 "
            "{%0,%1,%2,%3}, {%4,%5,%6,%7}, {%8,%9}, {%10,%11,%12,%13};"
            : "=f"(d0), "=f"(d1), "=f"(d2), "=f"(d3)
            : "r"(a0), "r"(a1), "r"(a2), "r"(a3), "r"(b0), "r"(b1),
              "f"(0.f), "f"(0.f), "f"(0.f), "f"(0.f));

        float2 njv = *(const float2*)&in2j[nb * 8 + cb];
        u64 njp = f2pack(njv.x, njv.y);
        u64 p01 = f2pack(d0, d1);
        u64 p23 = f2pack(d2, d3);
        u64 va = f2mul(f2mul(f2mul(p01, p01), nip0), njp);
        u64 vb = f2mul(f2mul(f2mul(p23, p23), nip1), njp);
        if (WITH_LOG) {
            va = f2add(va, eps2);
            vb = f2add(vb, eps2);
            u64 pr = f2mul(va, vb);
            float lo, hi; f2unpack(lo, hi, pr);
            float pp = lo * hi;                 // product of 4 entries >= ~1e-36
            int bits = __float_as_int(pp);
            esum += (bits >> 23) - 126;
            mprod *= __int_as_float((bits & 0x807FFFFF) | 0x3F000000);
        } else {
            accv = f2add(accv, f2add(va, vb));
        }
    }
    if (WITH_LOG) {
        local = __logf(mprod) + 0.69314718056f * (float)esum;
    } else {
        float lo, hi; f2unpack(lo, hi, accv);
        local = lo + hi;
    }
    __syncthreads();
    return local;
}

// Final reduction body (runs in the last gram block).
__device__ void final_reduce(float* __restrict__ out, int t)
{
    __shared__ double res[9];
    int w = t >> 5, l = t & 31;
    double s0 = 0.0, s1 = 0.0, s2 = 0.0, s3 = 0.0;
    if (w < 4) {
        int base = w * 544;
        for (int i = l; i < 544; i += 128) {
            s0 += g_part_par[base + i];
            if (i + 32 < 544) s1 += g_part_par[base + i + 32];
            if (i + 64 < 544) s2 += g_part_par[base + i + 64];
            if (i + 96 < 544) s3 += g_part_par[base + i + 96];
        }
    } else if (w == 4) {
        s0 = g_part_orth[l]; s1 = g_part_orth[l + 32]; s2 = g_part_orth[l + 64];
        if (l + 96 < 120) s3 = g_part_orth[l + 96];
    } else if (w == 5) {
        s0 = g_part_com[l]; s1 = g_part_com[l + 32]; s2 = g_part_com[l + 64];
        if (l + 96 < 120) s3 = g_part_com[l + 96];
    } else if (w == 6) {
        s0 = g_part_eq[l]; s1 = g_part_eq[l + 32]; s2 = g_part_eq[l + 64]; s3 = g_part_eq[l + 96];
    } else {
        s0 = g_part_sparse[l];       s1 = g_part_sparse[l + 32];
        s2 = g_part_sparse[l + 64];  s3 = g_part_sparse[l + 96];
        s0 += g_part_sparse[l + 128]; s1 += g_part_sparse[l + 160];
        s2 += g_part_sparse[l + 192]; s3 += g_part_sparse[l + 224];
    }
    double sum = (s0 + s1) + (s2 + s3);
#pragma unroll
    for (int o = 16; o; o >>= 1) sum += __shfl_down_sync(0xffffffffu, sum, o);
    if (l == 0) res[w] = sum;
    if (w == 6) {
        double sc = g_part_sec[l] + g_part_sec[l + 32];
#pragma unroll
        for (int o = 16; o; o >>= 1) sc += __shfl_down_sync(0xffffffffu, sc, o);
        if (l == 0) res[8] = sc;
    }
    __syncthreads();
    if (t == 0) {
        out[OFF_PAR]  = (float)((res[0] + res[1] + res[2] + res[3]) / 67108864.0);
        out[OFF_ORTH] = (float)(res[4] / (2048.0 * 2048.0));
        out[OFF_COM]  = (float)(res[5] / 16777216.0);
        out[OFF_EQ]   = (float)(res[6] / 1024.0);
        out[OFF_SPA]  = (float)(res[7] / 32768.0);
        out[OFF_SEC]  = (float)(res[8] / 64.0);
    }
}

// ---------------------------------------------------------------------------
// k_gram: parallel (0..2175) | orth (2176..2295).  Last block to finish also
// runs the final reduction (threadfence+atomic pattern), then resets g_done.
// ---------------------------------------------------------------------------
__global__ __launch_bounds__(256, 3) void k_gram(const int* __restrict__ sec_idx,
                                                 float* __restrict__ out)
{
    __shared__ __align__(16) float sm[3344];
    __shared__ int slast;
    int t = threadIdx.x;
    int bid = blockIdx.x;

    float local;
    double scale;
    double* slot;
    if (bid < 2176) {
        int s = bid / 136;
        int p = bid % 136;
        int ti = 0, len = 16;
        while (p >= len) { p -= len; len--; ti++; }
        int tj = ti + p;
        int rbaseI = s * 2048 + ti * 128;
        int rbaseJ = s * 2048 + tj * 128;
        local = gram_role<true>(g_diff + rbaseI * 16, g_diff + rbaseJ * 16,
                                g_n2 + rbaseI, g_n2 + rbaseJ, sm, t);
        scale = (ti == tj) ? -1.0 : -2.0;
        slot = &g_part_par[bid];
    } else {
        int p = bid - 2176;
        int si = 0, len = 15;
        while (p >= len) { p -= len; len--; si++; }
        int sj = si + 1 + p;
        int rbaseI = (si * 16 + sec_idx[si]) * 128;
        int rbaseJ = (sj * 16 + sec_idx[sj]) * 128;
        local = gram_role<false>(g_diff + rbaseI * 16, g_diff + rbaseJ * 16,
                                 g_n2 + rbaseI, g_n2 + rbaseJ, sm, t);
        scale = 2.0;
        slot = &g_part_orth[bid - 2176];
    }

    // block reduce + store
    {
        float v = local;
#pragma unroll
        for (int o = 16; o; o >>= 1) v += __shfl_xor_sync(0xffffffffu, v, o);
        float* sred = sm + 3328;
        if ((t & 31) == 0) sred[t >> 5] = v;
        __syncthreads();
        if (t == 0) {
            double tot = 0.0;
            for (int w = 0; w < 8; w++) tot += (double)sred[w];
            *slot = tot * scale;
        }
    }

    // last-block final reduction
    __threadfence();
    if (t == 0) {
        int old = atomicAdd(&g_done, 1);
        slast = (old == 2295) ? 1 : 0;
    }
    __syncthreads();
    if (slast) {
        final_reduce(out, t);
        if (t == 0) g_done = 0;   // reset for next graph replay
    }
}

extern "C" void kernel_launch(void* const* d_in, const int* in_sizes, int n_in,
                              void* d_out, int out_size)
{
    (void)in_sizes; (void)n_in; (void)out_size;
    const float* mean    = (const float*)d_in[0];
    const float* logvar  = (const float*)d_in[1];
    const float* z       = (const float*)d_in[2];
    const float* ge      = (const float*)d_in[3];
    const float* lw      = (const float*)d_in[4];
    const float* lb      = (const float*)d_in[5];
    const float* gum     = (const float*)d_in[6];
    const int*   sec_idx = (const int*)d_in[7];
    float* out = (float*)d_out;

    k_pre<<<376, 64>>>(ge, z, mean, logvar, lw, lb, gum, out);
    k_gram<<<2296, 256>>>(sec_idx, out);
}

// round 15
// speedup vs baseline: 1.5415x; 1.5415x over previous
#include <cuda_runtime.h>
#include <cuda_bf16.h>
#include <math.h>

#define TAU_INV 10000.0f

// Output layout (float32, flattened tuple)
#define OFF_TZ1  0
#define OFF_TZ2  1024
#define OFF_FWD  2048
#define OFF_EQ   18432
#define OFF_ATTN 18433
#define OFF_ORTH 35841
#define OFF_PAR  35842
#define OFF_COM  35843
#define OFF_SPA  35844
#define OFF_SEC  35845
#define OFF_SUB  35846

typedef unsigned long long u64;

// Packed f32x2 helpers
__device__ __forceinline__ u64 f2mul(u64 a, u64 b) {
    u64 d; asm("mul.rn.f32x2 %0,%1,%2;" : "=l"(d) : "l"(a), "l"(b)); return d;
}
__device__ __forceinline__ u64 f2add(u64 a, u64 b) {
    u64 d; asm("add.rn.f32x2 %0,%1,%2;" : "=l"(d) : "l"(a), "l"(b)); return d;
}
__device__ __forceinline__ u64 f2pack(float lo, float hi) {
    u64 d; asm("mov.b64 %0,{%1,%2};" : "=l"(d) : "f"(lo), "f"(hi)); return d;
}
__device__ __forceinline__ void f2unpack(float& lo, float& hi, u64 v) {
    asm("mov.b64 {%0,%1},%2;" : "=f"(lo), "=f"(hi) : "l"(v));
}
__device__ __forceinline__ unsigned pack_bf16(float lo, float hi) {
    unsigned r; asm("cvt.rn.bf16x2.f32 %0, %1, %2;" : "=r"(r) : "f"(hi), "f"(lo)); return r;
}
__device__ __forceinline__ unsigned s2u(const void* p) {
    unsigned a; asm("{ .reg .u64 t; cvta.to.shared.u64 t, %1; cvt.u32.u64 %0, t; }" : "=r"(a) : "l"(p)); return a;
}

// Scratch — deterministic slots, fully overwritten each replay.
__device__ unsigned g_diffn[256 * 128 * 8];   // normalized diff rows, bf16x2
__device__ double g_part_par[2176];
__device__ double g_part_orth[120];
__device__ double g_part_com[120];
__device__ double g_part_eq[128];
__device__ double g_part_sparse[256];
__device__ double g_part_sec[64];
__device__ int    g_done;          // static-init 0; last block resets it

// ---------------------------------------------------------------------------
// Warp-synchronous expm of 16x16 (scaling-and-squaring + 8-term Taylor).
// Lane l owns row r=l>>1, cols c0=(l&1)*8..+7.  ws = 960-float warp scratch.
// ---------------------------------------------------------------------------
__device__ __forceinline__ const float* expm16_warp(const float a8[8], float* ws,
                                                    int l, float r8[8])
{
    float* W0 = ws;
    float* W1 = ws + 320;
    float* W2 = ws + 640;
    int r = l >> 1, c0 = (l & 1) * 8;

    float cs[8];
#pragma unroll
    for (int j = 0; j < 8; j++) cs[j] = fabsf(a8[j]);
#pragma unroll
    for (int m = 2; m <= 16; m <<= 1)
#pragma unroll
        for (int j = 0; j < 8; j++) cs[j] += __shfl_xor_sync(0xffffffffu, cs[j], m);
    float nrm = fmaxf(fmaxf(fmaxf(cs[0], cs[1]), fmaxf(cs[2], cs[3])),
                      fmaxf(fmaxf(cs[4], cs[5]), fmaxf(cs[6], cs[7])));
    nrm = fmaxf(nrm, __shfl_xor_sync(0xffffffffu, nrm, 1));
    int s = 0;
    while (nrm > 0.25f && s < 40) { nrm *= 0.5f; s++; }
    float sc = ldexpf(1.0f, -s);

    float b8[8];
#pragma unroll
    for (int j = 0; j < 8; j++) {
        b8[j] = a8[j] * sc;
        r8[j] = ((c0 + j) == r ? 1.0f : 0.0f) + b8[j];
    }
    {
        float4* p0 = (float4*)&W0[r * 20 + c0];
        p0[0] = make_float4(b8[0], b8[1], b8[2], b8[3]);
        p0[1] = make_float4(b8[4], b8[5], b8[6], b8[7]);
        float4* p1 = (float4*)&W1[r * 20 + c0];
        p1[0] = make_float4(b8[0], b8[1], b8[2], b8[3]);
        p1[1] = make_float4(b8[4], b8[5], b8[6], b8[7]);
    }
    __syncwarp();

    float* Tc = W1; float* Tn = W2;
    for (int k = 2; k <= 8; k++) {
        float acc[8] = {0.f, 0.f, 0.f, 0.f, 0.f, 0.f, 0.f, 0.f};
#pragma unroll
        for (int d = 0; d < 16; d++) {
            float a = Tc[r * 20 + d];
            const float4* bv = (const float4*)&W0[d * 20 + c0];
            float4 x = bv[0], y = bv[1];
            acc[0] += a * x.x; acc[1] += a * x.y; acc[2] += a * x.z; acc[3] += a * x.w;
            acc[4] += a * y.x; acc[5] += a * y.y; acc[6] += a * y.z; acc[7] += a * y.w;
        }
        float ik = 1.0f / (float)k;
#pragma unroll
        for (int j = 0; j < 8; j++) { acc[j] *= ik; r8[j] += acc[j]; }
        float4* pt = (float4*)&Tn[r * 20 + c0];
        pt[0] = make_float4(acc[0], acc[1], acc[2], acc[3]);
        pt[1] = make_float4(acc[4], acc[5], acc[6], acc[7]);
        __syncwarp();
        float* tmp = Tc; Tc = Tn; Tn = tmp;
    }

    float* Sa = W0; float* Sb = Tn;
    {
        float4* ps = (float4*)&Sa[r * 20 + c0];
        ps[0] = make_float4(r8[0], r8[1], r8[2], r8[3]);
        ps[1] = make_float4(r8[4], r8[5], r8[6], r8[7]);
        __syncwarp();
    }
    for (int q = 0; q < s; q++) {
        float acc[8] = {0.f, 0.f, 0.f, 0.f, 0.f, 0.f, 0.f, 0.f};
#pragma unroll
        for (int d = 0; d < 16; d++) {
            float a = Sa[r * 20 + d];
            const float4* bv = (const float4*)&Sa[d * 20 + c0];
            float4 x = bv[0], y = bv[1];
            acc[0] += a * x.x; acc[1] += a * x.y; acc[2] += a * x.z; acc[3] += a * x.w;
            acc[4] += a * y.x; acc[5] += a * y.y; acc[6] += a * y.z; acc[7] += a * y.w;
        }
#pragma unroll
        for (int j = 0; j < 8; j++) r8[j] = acc[j];
        float4* ps = (float4*)&Sb[r * 20 + c0];
        ps[0] = make_float4(acc[0], acc[1], acc[2], acc[3]);
        ps[1] = make_float4(acc[4], acc[5], acc[6], acc[7]);
        __syncwarp();
        float* tmp = Sa; Sa = Sb; Sb = tmp;
    }
    return Sa;
}

// Block(256)-wide reduce -> *slot = scale * sum (no atomics)
__device__ __forceinline__ void block_reduce_store(float v, double scale,
                                                   double* slot, float* sred, int t)
{
#pragma unroll
    for (int o = 16; o; o >>= 1) v += __shfl_xor_sync(0xffffffffu, v, o);
    if ((t & 31) == 0) sred[t >> 5] = v;
    __syncthreads();
    if (t == 0) {
        double tot = 0.0;
        for (int w = 0; w < 8; w++) tot += (double)sred[w];
        *slot = tot * scale;
    }
}

// ---------------------------------------------------------------------------
// k_pre: 128 blocks x 2 warps; warp w handles e = bid*2+w.
// expm(ge[e]); diff rows; sparse; writes NORMALIZED bf16 rows to g_diffn.
// ---------------------------------------------------------------------------
__global__ __launch_bounds__(64) void k_pre(const float* __restrict__ ge,
                                            const float* __restrict__ z)
{
    __shared__ __align__(16) float sZ[128 * 20];
    __shared__ __align__(16) float ws[2][960];
    int t = threadIdx.x, l = t & 31, w = t >> 5;
    int e = blockIdx.x * 2 + w;
    int r = l >> 1, c0 = (l & 1) * 8;

    for (int i4 = t; i4 < 512; i4 += 64) {
        float4 v = ((const float4*)z)[i4];
        int m = i4 >> 2, q = i4 & 3;
        *(float4*)&sZ[m * 20 + q * 4] = v;
    }

    float a8[8];
    {
        const float4* gp = (const float4*)&ge[e * 256 + r * 16 + c0];
        float4 g0 = gp[0], g1 = gp[1];
        a8[0] = g0.x; a8[1] = g0.y; a8[2] = g0.z; a8[3] = g0.w;
        a8[4] = g1.x; a8[5] = g1.y; a8[6] = g1.z; a8[7] = g1.w;
    }
    float r8[8];
    const float* Rp = expm16_warp(a8, ws[w], l, r8);
    __syncthreads();

    float sparse_acc = 0.f;
    for (int k = 0; k < 8; k++) {
        int b = r + 16 * k;
        float acc[8] = {0.f, 0.f, 0.f, 0.f, 0.f, 0.f, 0.f, 0.f};
#pragma unroll
        for (int d = 0; d < 16; d++) {
            float zv = sZ[b * 20 + d];
            const float4* rv = (const float4*)&Rp[d * 20 + c0];
            float4 x = rv[0], y = rv[1];
            acc[0] += zv * x.x; acc[1] += zv * x.y; acc[2] += zv * x.z; acc[3] += zv * x.w;
            acc[4] += zv * y.x; acc[5] += zv * y.y; acc[6] += zv * y.z; acc[7] += zv * y.w;
        }
        const float4* zp = (const float4*)&sZ[b * 20 + c0];
        float4 z0 = zp[0], z1 = zp[1];
        float zc[8] = {z0.x, z0.y, z0.z, z0.w, z1.x, z1.y, z1.z, z1.w};
        float v8[8];
        float sum = 0.f, mx = 0.f;
#pragma unroll
        for (int j = 0; j < 8; j++) {
            v8[j] = zc[j] - acc[j];
            float v2 = v8[j] * v8[j];
            sum += v2;
            mx = fmaxf(mx, v2);
        }
        sum += __shfl_xor_sync(0xffffffffu, sum, 1);   // full-row norm^2
        mx = fmaxf(mx, __shfl_xor_sync(0xffffffffu, mx, 1));
        float inv = rsqrtf(sum);
        unsigned o0 = pack_bf16(v8[0] * inv, v8[1] * inv);
        unsigned o1 = pack_bf16(v8[2] * inv, v8[3] * inv);
        unsigned o2 = pack_bf16(v8[4] * inv, v8[5] * inv);
        unsigned o3 = pack_bf16(v8[6] * inv, v8[7] * inv);
        *(uint4*)&g_diffn[(e * 128 + b) * 8 + (l & 1) * 4] = make_uint4(o0, o1, o2, o3);
        if ((l & 1) == 0) {
            float sv = sum - mx;
            sparse_acc += sv * sv;
        }
    }
#pragma unroll
    for (int o = 16; o; o >>= 1) sparse_acc += __shfl_xor_sync(0xffffffffu, sparse_acc, o);
    if (l == 0) g_part_sparse[e] = (double)sparse_acc;
}

// ---------------------------------------------------------------------------
// Tensor-core Gram tile (128x128x16): rows are pre-normalized bf16, so the
// mma directly produces cosines. Zero LDS in the mainloop.
// smem: Pi32 @0 (1536 u32), Pj32 @1536 (1536 u32), sred @3072 (8 floats).
// ---------------------------------------------------------------------------
template <bool WITH_LOG>
__device__ __forceinline__ float gram_role(const unsigned* __restrict__ dnI,
                                           const unsigned* __restrict__ dnJ,
                                           float* sm, int t)
{
    unsigned* Pi32 = (unsigned*)sm;             // 128 rows x 12 u32 (48B stride)
    unsigned* Pj32 = (unsigned*)(sm + 1536);

    // stage: one uint4 per thread per matrix (row m halves)
    {
        int m = t >> 1, half = t & 1;
        uint4 vi = *(const uint4*)&dnI[t * 4];
        uint4 vj = *(const uint4*)&dnJ[t * 4];
        *(uint4*)&Pi32[m * 12 + half * 4] = vi;
        *(uint4*)&Pj32[m * 12 + half * 4] = vj;
    }
    __syncthreads();

    int lane = t & 31, w = t >> 5;
    int m0 = w * 16;

    unsigned a0, a1, a2, a3;
    {
        unsigned addr = s2u(Pi32) + (unsigned)((m0 + (lane & 15)) * 48 + (lane >> 4) * 16);
        asm volatile("ldmatrix.sync.aligned.m8n8.x4.shared.b16 {%0,%1,%2,%3}, [%4];"
                     : "=r"(a0), "=r"(a1), "=r"(a2), "=r"(a3) : "r"(addr));
    }
    unsigned pj_base = s2u(Pj32);

    const u64 eps2 = f2pack(1e-9f, 1e-9f);
    float local = 0.f;
    u64 accv = 0ull;
    float mprod = 1.0f;
    int   esum = 0;

#pragma unroll
    for (int nb = 0; nb < 16; nb++) {
        unsigned b0, b1;
        {
            int ln = lane & 15;
            unsigned addr = pj_base + (unsigned)((nb * 8 + (ln & 7)) * 48 + ((ln >> 3) & 1) * 16);
            asm volatile("ldmatrix.sync.aligned.m8n8.x2.shared.b16 {%0,%1}, [%2];"
                         : "=r"(b0), "=r"(b1) : "r"(addr));
        }
        float d0, d1, d2, d3;
        asm("mma.sync.aligned.m16n8k16.row.col.f32.bf16.bf16.f32 "
            "{%0,%1,%2,%3}, {%4,%5,%6,%7}, {%8,%9}, {%10,%11,%12,%13};"
            : "=f"(d0), "=f"(d1), "=f"(d2), "=f"(d3)
            : "r"(a0), "r"(a1), "r"(a2), "r"(a3), "r"(b0), "r"(b1),
              "f"(0.f), "f"(0.f), "f"(0.f), "f"(0.f));

        u64 p01 = f2pack(d0, d1);
        u64 p23 = f2pack(d2, d3);
        if (WITH_LOG) {
            u64 va = f2add(f2mul(p01, p01), eps2);
            u64 vb = f2add(f2mul(p23, p23), eps2);
            u64 pr = f2mul(va, vb);
            float lo, hi; f2unpack(lo, hi, pr);
            float pp = lo * hi;                 // product of 4 entries >= ~1e-36
            int bits = __float_as_int(pp);
            esum += (bits >> 23) - 126;
            mprod *= __int_as_float((bits & 0x807FFFFF) | 0x3F000000);
        } else {
            accv = f2add(accv, f2add(f2mul(p01, p01), f2mul(p23, p23)));
        }
    }
    if (WITH_LOG) {
        local = __logf(mprod) + 0.69314718056f * (float)esum;
    } else {
        float lo, hi; f2unpack(lo, hi, accv);
        local = lo + hi;
    }
    __syncthreads();
    return local;
}

// Final reduction body (runs in the last k_mega block).
__device__ void final_reduce(float* __restrict__ out, int t)
{
    __shared__ double res[9];
    int w = t >> 5, l = t & 31;
    double s0 = 0.0, s1 = 0.0, s2 = 0.0, s3 = 0.0;
    if (w < 4) {
        int base = w * 544;
        for (int i = l; i < 544; i += 128) {
            s0 += g_part_par[base + i];
            if (i + 32 < 544) s1 += g_part_par[base + i + 32];
            if (i + 64 < 544) s2 += g_part_par[base + i + 64];
            if (i + 96 < 544) s3 += g_part_par[base + i + 96];
        }
    } else if (w == 4) {
        s0 = g_part_orth[l]; s1 = g_part_orth[l + 32]; s2 = g_part_orth[l + 64];
        if (l + 96 < 120) s3 = g_part_orth[l + 96];
    } else if (w == 5) {
        s0 = g_part_com[l]; s1 = g_part_com[l + 32]; s2 = g_part_com[l + 64];
        if (l + 96 < 120) s3 = g_part_com[l + 96];
    } else if (w == 6) {
        s0 = g_part_eq[l]; s1 = g_part_eq[l + 32]; s2 = g_part_eq[l + 64]; s3 = g_part_eq[l + 96];
    } else {
        s0 = g_part_sparse[l];       s1 = g_part_sparse[l + 32];
        s2 = g_part_sparse[l + 64];  s3 = g_part_sparse[l + 96];
        s0 += g_part_sparse[l + 128]; s1 += g_part_sparse[l + 160];
        s2 += g_part_sparse[l + 192]; s3 += g_part_sparse[l + 224];
    }
    double sum = (s0 + s1) + (s2 + s3);
#pragma unroll
    for (int o = 16; o; o >>= 1) sum += __shfl_down_sync(0xffffffffu, sum, o);
    if (l == 0) res[w] = sum;
    if (w == 6) {
        double sc = g_part_sec[l] + g_part_sec[l + 32];
#pragma unroll
        for (int o = 16; o; o >>= 1) sc += __shfl_down_sync(0xffffffffu, sc, o);
        if (l == 0) res[8] = sc;
    }
    __syncthreads();
    if (t == 0) {
        out[OFF_PAR]  = (float)((res[0] + res[1] + res[2] + res[3]) / 67108864.0);
        out[OFF_ORTH] = (float)(res[4] / (2048.0 * 2048.0));
        out[OFF_COM]  = (float)(res[5] / 16777216.0);
        out[OFF_EQ]   = (float)(res[6] / 1024.0);
        out[OFF_SPA]  = (float)(res[7] / 32768.0);
        out[OFF_SEC]  = (float)(res[8] / 64.0);
    }
}

// ---------------------------------------------------------------------------
// k_mega: commut (0..119) | main (120..247) | gram: parallel/orth (248..2543).
// Last block to finish runs the final reduction, then resets g_done.
// ---------------------------------------------------------------------------
__global__ __launch_bounds__(256, 3) void k_mega(
    const int* __restrict__ sec_idx, const float* __restrict__ ge,
    const float* __restrict__ mean, const float* __restrict__ logvar,
    const float* __restrict__ z, const float* __restrict__ lw,
    const float* __restrict__ lb, const float* __restrict__ gum,
    float* __restrict__ out)
{
    __shared__ __align__(16) float sm[3088];
    __shared__ int slast;
    int t = threadIdx.x;
    int bid = blockIdx.x;

    if (bid < 120) {
        // ---- commut: 120 (a,b) pairs, cumsum weight (120 - q)
        int q = bid;
        float* Ga = sm;        float* Gb = sm + 256;
        float* Ha = sm + 512;  float* Hb = sm + 768;
        float* sred = sm + 1024;
        int p = q, a = 0, len = 15;
        while (p >= len) { p -= len; len--; a++; }
        int b = a + 1 + p;

        int k = t >> 4, j = t & 15;
        Ga[t] = ge[a * 256 + t];
        Gb[t] = ge[b * 256 + t];
        Ha[t] = ge[k * 4096 + a * 16 + j];
        Hb[t] = ge[k * 4096 + b * 16 + j];
        __syncthreads();

        int i = t >> 4;
        float R1 = 0.f, R2 = 0.f;
#pragma unroll
        for (int kk = 0; kk < 16; kk++) {
            R1 += Ga[i * 16 + kk] * Hb[kk * 16 + j];
            R2 += Gb[i * 16 + kk] * Ha[kk * 16 + j];
        }
        float d = R1 - R2;
        block_reduce_store(d * d, 2.0 * (double)(120 - q), &g_part_com[q], sred, t);
    } else if (bid < 248) {
        // ---- main branch: mbid&63 = batch row, mbid>>6 = fwd/inv
        int mbid = bid - 120;
        int b = mbid & 63;
        int dir = mbid >> 6;
        float* feat    = sm;           // 64
        float* probS   = sm + 64;      // 288
        float* sw      = sm + 352;     // 16
        float* fp      = sm + 368;     // 256
        float* wv      = sm + 624;     // 256
        float* z1v     = sm + 880;     // 16
        float* z2v     = sm + 896;     // 16
        float* lossArr = sm + 912;     // 16
        float* A       = sm + 928;     // 256
        float* ws      = sm + 1184;    // 960 warp0 expm scratch

        if (t < 16) {
            feat[t]      = mean[b * 16 + t];
            feat[16 + t] = __expf(0.5f * logvar[b * 16 + t]);
            feat[32 + t] = mean[(64 + b) * 16 + t];
            feat[48 + t] = __expf(0.5f * mean[(64 + b) * 16 + t]);   // ref uses mean (sic)
            z1v[t] = z[b * 16 + t];
            z2v[t] = z[(64 + b) * 16 + t];
        }
        __syncthreads();

        for (int c = t; c < 288; c += 256) {
            float acc = lb[c];
#pragma unroll 16
            for (int kk = 0; kk < 64; kk++) acc += feat[kk] * lw[c * 64 + kk];
            probS[c] = acc;
        }
        __syncthreads();

        if (t < 16) {
            int s = t;
            float l0 = probS[2 * s], l1 = probS[2 * s + 1];
            float m2 = fmaxf(l0, l1);
            float e0 = __expf(l0 - m2), e1 = __expf(l1 - m2);
            float inv = 1.0f / (e0 + e1);
            float p0 = e0 * inv, p1 = e1 * inv;
            float pm = fmaxf(p0, p1);
            float lse = pm + __logf(__expf(p0 - pm) + __expf(p1 - pm));
            float zd = z1v[s] - z2v[s];
            int tgt = (fabsf(zd) > 0.2f) ? 1 : 0;
            lossArr[s] = -((tgt ? p1 : p0) - lse);
            float g0 = gum[(b * 16 + s) * 2], g1 = gum[(b * 16 + s) * 2 + 1];
            float x0 = l0 + g0, x1 = l1 + g1;
            float mm = fmaxf(x0, x1);
            float a0 = __expf((x0 - mm) * TAU_INV);
            float a1 = __expf((x1 - mm) * TAU_INV);
            float as = a0 + a1;
            a0 /= as; a1 /= as;
            sw[s] = (a0 >= 0.5f || a1 > 0.5f) ? a1 : 0.0f;
            int base = 32 + s * 16;
            float mx = -1e30f;
            for (int u = 0; u < 16; u++) mx = fmaxf(mx, probS[base + u]);
            float smx = 0.f;
            for (int u = 0; u < 16; u++) smx += __expf(probS[base + u] - mx);
            float isv = 1.0f / smx;
            for (int u = 0; u < 16; u++) fp[s * 16 + u] = __expf(probS[base + u] - mx) * isv;
        }
        __syncthreads();

        if (dir == 0) {
            if (t == 0) {
                float sl = 0.f;
                for (int s2 = 0; s2 < 16; s2++) sl += lossArr[s2];
                g_part_sec[b] = (double)sl;
            }
            if (t < 16) out[OFF_ATTN + b * 272 + t] = sw[t];
            out[OFF_ATTN + b * 272 + 16 + t] = fp[t];
        }
        wv[t] = sw[t >> 4] * fp[t];
        __syncthreads();

        {
            float Ssum = 0.f;
            for (int s2 = 0; s2 < 16; s2++) {
                float acc = 0.f;
#pragma unroll
                for (int u = 0; u < 16; u++)
                    acc += wv[s2 * 16 + u] * ge[(s2 * 16 + u) * 256 + t];
                if (dir == 0) out[OFF_SUB + b * 4096 + s2 * 256 + t] = acc;
                Ssum += acc;
            }
            A[t] = Ssum;
        }
        __syncthreads();   // A published; warps 1..7 are done

        if (t < 32) {
            int l = t;
            int r = l >> 1, c0 = (l & 1) * 8;
            float sign = (dir == 0) ? 1.0f : -1.0f;
            float a8[8];
            {
                const float4* ap = (const float4*)&A[r * 16 + c0];
                float4 a0 = ap[0], a1 = ap[1];
                a8[0] = sign * a0.x; a8[1] = sign * a0.y; a8[2] = sign * a0.z; a8[3] = sign * a0.w;
                a8[4] = sign * a1.x; a8[5] = sign * a1.y; a8[6] = sign * a1.z; a8[7] = sign * a1.w;
            }
            float r8[8];
            const float* Rp = expm16_warp(a8, ws, l, r8);
            (void)Rp;
            if (dir == 0) {
                float4* op = (float4*)&out[OFF_FWD + b * 256 + r * 16 + c0];
                op[0] = make_float4(r8[0], r8[1], r8[2], r8[3]);
                op[1] = make_float4(r8[4], r8[5], r8[6], r8[7]);
            }
            const float* zsrc = (dir == 0) ? z1v : z2v;
            const float* zoth = (dir == 0) ? z2v : z1v;
            float zr = zsrc[r];
            float p8[8];
#pragma unroll
            for (int j = 0; j < 8; j++) p8[j] = zr * r8[j];
#pragma unroll
            for (int m = 2; m <= 16; m <<= 1)
#pragma unroll
                for (int j = 0; j < 8; j++) p8[j] += __shfl_xor_sync(0xffffffffu, p8[j], m);
            if (l < 2) {
                float4* tp = (float4*)&out[(dir == 0 ? OFF_TZ1 : OFF_TZ2) + b * 16 + c0];
                tp[0] = make_float4(p8[0], p8[1], p8[2], p8[3]);
                tp[1] = make_float4(p8[4], p8[5], p8[6], p8[7]);
            }
            float eqs = 0.f;
#pragma unroll
            for (int j = 0; j < 8; j++) {
                float d1 = p8[j] - zoth[c0 + j];
                eqs += d1 * d1;
            }
            eqs += __shfl_xor_sync(0xffffffffu, eqs, 1);
            if (l == 0) g_part_eq[mbid] = (double)eqs;
        }
    } else {
        int g = bid - 248;
        if (g < 2176) {
            int s = g / 136;
            int p = g % 136;
            int ti = 0, len = 16;
            while (p >= len) { p -= len; len--; ti++; }
            int tj = ti + p;
            int rbaseI = s * 2048 + ti * 128;
            int rbaseJ = s * 2048 + tj * 128;
            float local = gram_role<true>(g_diffn + rbaseI * 8, g_diffn + rbaseJ * 8, sm, t);
            double w = (ti == tj) ? -1.0 : -2.0;
            block_reduce_store(local, w, &g_part_par[g], sm + 3072, t);
        } else {
            int p = g - 2176;
            int si = 0, len = 15;
            while (p >= len) { p -= len; len--; si++; }
            int sj = si + 1 + p;
            int rbaseI = (si * 16 + sec_idx[si]) * 128;
            int rbaseJ = (sj * 16 + sec_idx[sj]) * 128;
            float local = gram_role<false>(g_diffn + rbaseI * 8, g_diffn + rbaseJ * 8, sm, t);
            block_reduce_store(local, 2.0, &g_part_orth[g - 2176], sm + 3072, t);
        }
    }

    // last-block final reduction (all 2544 blocks participate in the count)
    __threadfence();
    if (t == 0) {
        int old = atomicAdd(&g_done, 1);
        slast = (old == 2543) ? 1 : 0;
    }
    __syncthreads();
    if (slast) {
        final_reduce(out, t);
        if (t == 0) g_done = 0;   // reset for next graph replay
    }
}

extern "C" void kernel_launch(void* const* d_in, const int* in_sizes, int n_in,
                              void* d_out, int out_size)
{
    (void)in_sizes; (void)n_in; (void)out_size;
    const float* mean    = (const float*)d_in[0];
    const float* logvar  = (const float*)d_in[1];
    const float* z       = (const float*)d_in[2];
    const float* ge      = (const float*)d_in[3];
    const float* lw      = (const float*)d_in[4];
    const float* lb      = (const float*)d_in[5];
    const float* gum     = (const float*)d_in[6];
    const int*   sec_idx = (const int*)d_in[7];
    float* out = (float*)d_out;

    k_pre<<<128, 64>>>(ge, z);
    k_mega<<<2544, 256>>>(sec_idx, ge, mean, logvar, z, lw, lb, gum, out);
}